// round 15
// baseline (speedup 1.0000x reference)
#include <cuda_runtime.h>
#include <cuda_bf16.h>
#include <math.h>
#include <stdint.h>

#define G    148
#define OO   1152
typedef unsigned long long ull;

// ---------------- scratch ----------------
__device__ float g_Pw1[6 * 64 * 1024];     // slices 0-4: ctx K-split; slice 5: sample
__device__ float g_Pgh[4 * 64 * 3072];
__device__ float g_Pgi[6 * 64 * 3072];
__device__ float g_Pq1[24 * 64 * 1024];    // 0-15 det-part, 16-23 x-part
__device__ float g_Pq2[16 * 64 * 1024];
__device__ float g_Ph [16 * 64 * 256];
__device__ float g_det[2 * 64 * 1024];
__device__ float g_out1[64 * 6 * OO];
__device__ float g_out2[64 * 1 * OO];
__device__ unsigned g_grp[512][8];
__device__ unsigned g_root[512];

// ---------------- helpers ----------------
__device__ __forceinline__ float eluf(float x)  { return x > 0.f ? x : (expf(x) - 1.f); }
__device__ __forceinline__ float sigm(float x)  { return 1.f / (1.f + expf(-x)); }
__device__ __forceinline__ float softp(float x) { return x > 20.f ? x : log1pf(expf(x)); }

__device__ __forceinline__ float4 ldcg4(const float *p) {
    return __ldcg((const float4 *)p);
}

// Two-level replay-safe grid barrier (R9-proven), no trailing acquire fence:
// cross-phase data is read via ldcg4 (L2 is the coherence point).
__device__ __forceinline__ void gridbar(int slot) {
    __syncthreads();
    if (threadIdx.x == 0) {
        __threadfence();
        const int g = blockIdx.x & 7;
        const unsigned gsz = (g < 4) ? 19u : 18u;   // 4*19 + 4*18 = 148
        unsigned old = atomicAdd(&g_grp[slot][g], 1u);
        unsigned r = old / gsz;
        if (old % gsz == gsz - 1u)
            atomicAdd(&g_root[slot], 1u);
        unsigned target = (r + 1u) * 8u;
        volatile unsigned *p = &g_root[slot];
        while (*p < target) { }
    }
    __syncthreads();
}

__device__ __forceinline__ unsigned su32(const void *p) {
    return (unsigned)__cvta_generic_to_shared(p);
}
__device__ __forceinline__ void ldm4(unsigned addr, unsigned *r) {
    asm volatile("ldmatrix.sync.aligned.m8n8.x4.shared.b16 {%0,%1,%2,%3}, [%4];"
                 : "=r"(r[0]), "=r"(r[1]), "=r"(r[2]), "=r"(r[3]) : "r"(addr));
}
__device__ __forceinline__ void ldm4t(unsigned addr, unsigned *r) {
    asm volatile("ldmatrix.sync.aligned.m8n8.x4.trans.shared.b16 {%0,%1,%2,%3}, [%4];"
                 : "=r"(r[0]), "=r"(r[1]), "=r"(r[2]), "=r"(r[3]) : "r"(addr));
}
#define MMA(cp, a, b0, b1)                                                          \
    asm volatile("mma.sync.aligned.m16n8k16.row.col.f32.bf16.bf16.f32 "             \
                 "{%0,%1,%2,%3},{%4,%5,%6,%7},{%8,%9},{%0,%1,%2,%3};"               \
                 : "+f"((cp)[0]), "+f"((cp)[1]), "+f"((cp)[2]), "+f"((cp)[3])       \
                 : "r"((a)[0]), "r"((a)[1]), "r"((a)[2]), "r"((a)[3]),              \
                   "r"(b0), "r"(b1))

__device__ __forceinline__ void split4(float4 v, unsigned *hi, unsigned *lo) {
    __nv_bfloat162 h0 = __floats2bfloat162_rn(v.x, v.y);
    __nv_bfloat162 h1 = __floats2bfloat162_rn(v.z, v.w);
    float rx = v.x - __bfloat162float(h0.x), ry = v.y - __bfloat162float(h0.y);
    float rz = v.z - __bfloat162float(h1.x), rw = v.w - __bfloat162float(h1.y);
    __nv_bfloat162 l0 = __floats2bfloat162_rn(rx, ry);
    __nv_bfloat162 l1 = __floats2bfloat162_rn(rz, rw);
    hi[0] = *reinterpret_cast<unsigned *>(&h0);
    hi[1] = *reinterpret_cast<unsigned *>(&h1);
    lo[0] = *reinterpret_cast<unsigned *>(&l0);
    lo[1] = *reinterpret_cast<unsigned *>(&l1);
}

// ---------------- 64x128 tensor-core GEMM tile (3xBF16, fp32 accuracy) ------
#define APITCH 24
#define BPITCH 136
#define ASZ    (64 * APITCH)
#define BSZ    (16 * BPITCH)

// RED=0: A = [A1 (K1 cols) | A2 at k-K1].
// RED=1: A = elu(sum_{s<RSK} RP_s + Rb1)   (RP rows 1024)
// RED=2: A = (sum_{16} Ph.mean + Rb1) + (softp(sum Ph.std + Rb2)+1e-4)*Rnq
//        (RP rows 256, std at +128; used with K=128, k0=0)
template <int RED>
__device__ __forceinline__ void gemm_tile(
    const float *A1, int lda1, int K1, const float *A2, int lda2,
    const float *RP, int RSK, const float *Rb1, const float *Rb2,
    const float *Rnq, int Rldnq,
    const float *W1, const float *W2, int wsplit, int ldw,
    float *Pslice, int ldP, int n0, int k0, int nchunks,
    unsigned short *sA, unsigned short *sB)
{
    const int tid  = threadIdx.x;
    const int lane = tid & 31;
    const int w    = tid >> 5;
    const int wm   = w >> 2;
    const int wn   = w & 3;
    const int arow = tid >> 2;
    const int akq  = (tid & 3) * 4;

    float acc[2][4][4];
#pragma unroll
    for (int i = 0; i < 2; ++i)
#pragma unroll
        for (int j = 0; j < 4; ++j)
#pragma unroll
            for (int q = 0; q < 4; ++q) acc[i][j][q] = 0.f;

    auto loadA = [&](int kb) -> float4 {
        int k = kb + akq;
        float4 v = make_float4(0.f, 0.f, 0.f, 0.f);
        if (RED == 1) {
            const float *p = RP + (size_t)arow * 1024 + k;
            for (int s = 0; s < RSK; ++s) {
                float4 t = ldcg4(p + (size_t)s * 64 * 1024);
                v.x += t.x; v.y += t.y; v.z += t.z; v.w += t.w;
            }
            float4 b = *(const float4 *)(Rb1 + k);
            v.x = eluf(v.x + b.x); v.y = eluf(v.y + b.y);
            v.z = eluf(v.z + b.z); v.w = eluf(v.w + b.w);
        } else if (RED == 2) {
            const float *p = RP + (size_t)arow * 256 + k;
            float4 m = make_float4(0.f, 0.f, 0.f, 0.f), sd = m;
            for (int s = 0; s < 16; ++s) {
                float4 t0 = ldcg4(p + (size_t)s * 64 * 256);
                float4 t1 = ldcg4(p + (size_t)s * 64 * 256 + 128);
                m.x += t0.x; m.y += t0.y; m.z += t0.z; m.w += t0.w;
                sd.x += t1.x; sd.y += t1.y; sd.z += t1.z; sd.w += t1.w;
            }
            float4 bm = *(const float4 *)(Rb1 + k);
            float4 bs = *(const float4 *)(Rb2 + k);
            float4 e  = *(const float4 *)(Rnq + (size_t)arow * Rldnq + k);
            v.x = (m.x + bm.x) + (softp(sd.x + bs.x) + 1e-4f) * e.x;
            v.y = (m.y + bm.y) + (softp(sd.y + bs.y) + 1e-4f) * e.y;
            v.z = (m.z + bm.z) + (softp(sd.z + bs.z) + 1e-4f) * e.z;
            v.w = (m.w + bm.w) + (softp(sd.w + bs.w) + 1e-4f) * e.w;
        } else {
            if (k < K1) {
                if (A1) v = ldcg4(A1 + (size_t)arow * lda1 + k);
            } else {
                if (A2) v = ldcg4(A2 + (size_t)arow * lda2 + (k - K1));
            }
        }
        return v;
    };

    float4 wV[2];
    auto loadW = [&](int kb) {
#pragma unroll
        for (int i = 0; i < 2; ++i) {
            int unit = tid + 256 * i;
            int wr = unit >> 5;
            int wc = (unit & 31) * 4;
            int col = n0 + wc;
            const float *wp = (col < wsplit)
                ? (W1 + (size_t)(kb + wr) * ldw + col)
                : (W2 + (size_t)(kb + wr) * ldw + (col - wsplit));
            wV[i] = *(const float4 *)wp;
        }
    };
    auto storeAB = [&](int p, float4 aV) {
        unsigned hi[2], lo[2];
        split4(aV, hi, lo);
        unsigned short *da = sA + (size_t)p * 2 * ASZ + arow * APITCH + akq;
        *(uint2 *)da = make_uint2(hi[0], hi[1]);
        *(uint2 *)(da + ASZ) = make_uint2(lo[0], lo[1]);
#pragma unroll
        for (int i = 0; i < 2; ++i) {
            int unit = tid + 256 * i;
            int wr = unit >> 5;
            int wc = (unit & 31) * 4;
            split4(wV[i], hi, lo);
            unsigned short *db = sB + (size_t)p * 2 * BSZ + wr * BPITCH + wc;
            *(uint2 *)db = make_uint2(hi[0], hi[1]);
            *(uint2 *)(db + BSZ) = make_uint2(lo[0], lo[1]);
        }
    };

    const int gq = lane >> 3, rq = lane & 7;
    const unsigned aLane = ((wm * 32 + (gq & 1) * 8 + rq) * APITCH + (gq >> 1) * 8) * 2;
    const unsigned bLane = (((gq & 1) * 8 + rq) * BPITCH + wn * 32 + (gq >> 1) * 8) * 2;
    const unsigned sAu = su32(sA), sBu = su32(sB);

    float4 aV = loadA(k0);
    loadW(k0);
    storeAB(0, aV);
    __syncthreads();

    for (int c = 0; c < nchunks; ++c) {
        const int p = c & 1;
        if (c + 1 < nchunks) {
            int kb = k0 + (c + 1) * 16;
            aV = loadA(kb);
            loadW(kb);
        }
        unsigned baseAhi = sAu + p * (2 * ASZ * 2);
        unsigned baseAlo = baseAhi + ASZ * 2;
        unsigned baseBhi = sBu + p * (2 * BSZ * 2);
        unsigned baseBlo = baseBhi + BSZ * 2;
        unsigned ah[2][4], al[2][4], bh[8], bl[8];
        ldm4(baseAhi + aLane, ah[0]);
        ldm4(baseAhi + aLane + 16 * APITCH * 2, ah[1]);
        ldm4(baseAlo + aLane, al[0]);
        ldm4(baseAlo + aLane + 16 * APITCH * 2, al[1]);
        ldm4t(baseBhi + bLane, bh);
        ldm4t(baseBhi + bLane + 32, bh + 4);
        ldm4t(baseBlo + bLane, bl);
        ldm4t(baseBlo + bLane + 32, bl + 4);
#pragma unroll
        for (int mt = 0; mt < 2; ++mt) {
#pragma unroll
            for (int nt = 0; nt < 4; ++nt) {
                unsigned b0 = bh[nt * 2], b1 = bh[nt * 2 + 1];
                MMA(acc[mt][nt], ah[mt], b0, b1);
                MMA(acc[mt][nt], ah[mt], bl[nt * 2], bl[nt * 2 + 1]);
                MMA(acc[mt][nt], al[mt], b0, b1);
            }
        }
        if (c + 1 < nchunks) storeAB(p ^ 1, aV);
        __syncthreads();
    }

    const int tr = lane >> 2, tc = (lane & 3) * 2;
#pragma unroll
    for (int mt = 0; mt < 2; ++mt) {
#pragma unroll
        for (int nt = 0; nt < 4; ++nt) {
            int row = wm * 32 + mt * 16 + tr;
            int col = n0 + wn * 32 + nt * 8 + tc;
            *(float2 *)&Pslice[(size_t)row * ldP + col] =
                make_float2(acc[mt][nt][0], acc[mt][nt][1]);
            *(float2 *)&Pslice[(size_t)(row + 8) * ldP + col] =
                make_float2(acc[mt][nt][2], acc[mt][nt][3]);
        }
    }
}

// ---------------- kernel ----------------
struct Args {
    const float *X[3], *NQ[3];
    const float *w1, *b1, *gwi, *gwh, *gbi, *gbh;
    const float *q1, *qb1, *q2, *qb2, *wqm, *bqm, *wqs, *bqs;
    float *out0;
};

// Sample writer: reduce Ph (16 slices, ldcg), reparam, write out[:, tw, 0:128].
__device__ __forceinline__ void write_sample(
    int lidx, const float *bqml, const float *bqsl,
    const float *NQ, int T, int tw, float *out_l)
{
    int b = lidx >> 5;
    int c = (lidx & 31) << 2;
    float4 m = make_float4(0,0,0,0), sp = m;
    for (int s = 0; s < 16; ++s) {
        const float *base = g_Ph + ((size_t)s * 64 + b) * 256;
        float4 p0 = ldcg4(base + c);
        float4 p1 = ldcg4(base + 128 + c);
        m.x += p0.x; m.y += p0.y; m.z += p0.z; m.w += p0.w;
        sp.x += p1.x; sp.y += p1.y; sp.z += p1.z; sp.w += p1.w;
    }
    float4 bm = *(const float4 *)(bqml + c);
    float4 bs = *(const float4 *)(bqsl + c);
    float4 e  = *(const float4 *)(NQ + (size_t)b * T * 128 + (size_t)tw * 128 + c);
    float4 o;
    o.x = (m.x + bm.x) + (softp(sp.x + bs.x) + 1e-4f) * e.x;
    o.y = (m.y + bm.y) + (softp(sp.y + bs.y) + 1e-4f) * e.y;
    o.z = (m.z + bm.z) + (softp(sp.z + bs.z) + 1e-4f) * e.z;
    o.w = (m.w + bm.w) + (softp(sp.w + bs.w) + 1e-4f) * e.w;
    *(float4 *)(out_l + (size_t)b * T * OO + (size_t)tw * OO + c) = o;
}

__global__ __launch_bounds__(256, 1) void cwvae_persist(Args a) {
    __shared__ __align__(16) unsigned short sA[2 * 2 * ASZ];
    __shared__ __align__(16) unsigned short sB[2 * 2 * BSZ];
    const int bx  = blockIdx.x;
    const int tid = threadIdx.x;
    int slot = 0;

    for (int l = 2; l >= 0; --l) {
        const int T   = (l == 0) ? 36 : (l == 1) ? 6 : 1;
        const int Tup = (l == 0) ? 6 : 1;
        const float *X  = a.X[l];
        const float *NQ = a.NQ[l];
        float *out_l = (l == 0) ? a.out0 : (l == 1) ? g_out1 : g_out2;
        const float *out_up = (l == 0) ? g_out1 : (l == 1) ? g_out2 : nullptr;

        const float *w1l  = a.w1  + (size_t)l * 1280 * 1024;
        const float *b1l  = a.b1  + (size_t)l * 1024;
        const float *gwil = a.gwi + (size_t)l * 1024 * 3072;
        const float *gwhl = a.gwh + (size_t)l * 1024 * 3072;
        const float *gbil = a.gbi + (size_t)l * 3072;
        const float *gbhl = a.gbh + (size_t)l * 3072;
        const float *q1l  = a.q1  + (size_t)l * 2048 * 1024;
        const float *qb1l = a.qb1 + (size_t)l * 1024;
        const float *q2l  = a.q2  + (size_t)l * 1024 * 1024;
        const float *qb2l = a.qb2 + (size_t)l * 1024;
        const float *wqml = a.wqm + (size_t)l * 1024 * 128;
        const float *bqml = a.bqm + (size_t)l * 128;
        const float *wqsl = a.wqs + (size_t)l * 1024 * 128;
        const float *bqsl = a.bqs + (size_t)l * 128;

        {   // zero det[0] and Pw1 sample slice (slice 5)
            int idx = bx * 256 + tid;
            if (idx < 16384) {
                *(float4 *)&g_det[idx * 4] = make_float4(0.f, 0.f, 0.f, 0.f);
                *(float4 *)&g_Pw1[5 * 64 * 1024 + idx * 4] = make_float4(0.f, 0.f, 0.f, 0.f);
            }
        }
        gridbar(slot++);

        int cur = 0;
        for (int t = 0; t < T; ++t) {
            const int nxt = cur ^ 1;
            const float *ctx = out_up ? out_up + (size_t)(t / 6) * OO : nullptr;

            // P1: w1_ctx (blocks 0..39, slices 0-4) + gh (40..135)
            //     + w1_samp RED2 -> Pw1 slice 5 (136..143, t>0)
            if (bx < 40) {
                int ntile = bx / 5, s = bx % 5;
                int k0  = 128 + ((s < 4) ? s * 224 : 896);   // 128,352,576,800,1024
                int nch = (s < 4) ? 14 : 16;
                gemm_tile<0>(nullptr, 0, 128, ctx, Tup * OO,
                             nullptr, 0, nullptr, nullptr, nullptr, 0,
                             w1l, nullptr, 1 << 30, 1024,
                             g_Pw1 + (size_t)s * 64 * 1024, 1024,
                             ntile * 128, k0, nch, sA, sB);
            } else if (bx < 136) {
                int jj = bx - 40, ntile = jj >> 2, s = jj & 3;
                gemm_tile<0>(g_det + (size_t)cur * 65536, 1024, 1024, nullptr, 0,
                             nullptr, 0, nullptr, nullptr, nullptr, 0,
                             gwhl, nullptr, 1 << 30, 3072,
                             g_Pgh + (size_t)s * 64 * 3072, 3072,
                             ntile * 128, s * 256, 16, sA, sB);
            } else if (bx < 144) {
                if (t > 0) {
                    int ntile = bx - 136;
                    gemm_tile<2>(nullptr, 0, 0, nullptr, 0,
                                 g_Ph, 16, bqml, bqsl,
                                 NQ + (size_t)(t - 1) * 128, T * 128,
                                 w1l, nullptr, 1 << 30, 1024,
                                 g_Pw1 + (size_t)5 * 64 * 1024, 1024,
                                 ntile * 128, 0, 8, sA, sB);
                }
            }
            gridbar(slot++);

            // P2: gi (144 jobs, reduce Pw1{6}) || sample-writer(t-1) (144..147)
            if (bx < 144) {
                int ntile = bx / 6, s = bx % 6;
                int k0  = (s < 4) ? s * 176 : (704 + (s - 4) * 160);
                int nch = (s < 4) ? 11 : 10;
                gemm_tile<1>(nullptr, 0, 0, nullptr, 0,
                             g_Pw1, 6, b1l, nullptr, nullptr, 0,
                             gwil, nullptr, 1 << 30, 3072,
                             g_Pgi + (size_t)s * 64 * 3072, 3072,
                             ntile * 128, k0, nch, sA, sB);
            } else if (t > 0) {
                int base = (bx - 144) * 256 + tid;
                write_sample(base, bqml, bqsl, NQ, T, t - 1, out_l);
                write_sample(base + 1024, bqml, bqsl, NQ, T, t - 1, out_l);
            }
            gridbar(slot++);

            // P3: GRU (blocks 0..63) || q1 x-part (64..127; X-only dependency)
            if (bx < 64) {
                int idx = bx * 256 + tid;
                int b = idx >> 8;
                int j = (idx & 255) << 2;
                float4 gir = make_float4(0,0,0,0), giz = gir, gin = gir;
                float4 ghr = gir, ghz = gir, ghn = gir;
                for (int s = 0; s < 6; ++s) {
                    const float *base = g_Pgi + ((size_t)s * 64 + b) * 3072;
                    float4 p;
                    p = ldcg4(base + j);        gir.x+=p.x; gir.y+=p.y; gir.z+=p.z; gir.w+=p.w;
                    p = ldcg4(base + 1024 + j); giz.x+=p.x; giz.y+=p.y; giz.z+=p.z; giz.w+=p.w;
                    p = ldcg4(base + 2048 + j); gin.x+=p.x; gin.y+=p.y; gin.z+=p.z; gin.w+=p.w;
                }
                for (int s = 0; s < 4; ++s) {
                    const float *base = g_Pgh + ((size_t)s * 64 + b) * 3072;
                    float4 p;
                    p = ldcg4(base + j);        ghr.x+=p.x; ghr.y+=p.y; ghr.z+=p.z; ghr.w+=p.w;
                    p = ldcg4(base + 1024 + j); ghz.x+=p.x; ghz.y+=p.y; ghz.z+=p.z; ghz.w+=p.w;
                    p = ldcg4(base + 2048 + j); ghn.x+=p.x; ghn.y+=p.y; ghn.z+=p.z; ghn.w+=p.w;
                }
                float4 bir = *(const float4 *)(gbil + j),        bhr = *(const float4 *)(gbhl + j);
                float4 biz = *(const float4 *)(gbil + 1024 + j), bhz = *(const float4 *)(gbhl + 1024 + j);
                float4 bin = *(const float4 *)(gbil + 2048 + j), bhn = *(const float4 *)(gbhl + 2048 + j);
                float4 dv  = ldcg4(g_det + (size_t)cur * 65536 + (size_t)b * 1024 + j);
                float o[4];
                {
                    float gi_r[4] = {gir.x, gir.y, gir.z, gir.w}, gi_z[4] = {giz.x, giz.y, giz.z, giz.w};
                    float gi_n[4] = {gin.x, gin.y, gin.z, gin.w};
                    float gh_r[4] = {ghr.x, ghr.y, ghr.z, ghr.w}, gh_z[4] = {ghz.x, ghz.y, ghz.z, ghz.w};
                    float gh_n[4] = {ghn.x, ghn.y, ghn.z, ghn.w};
                    float bi_r[4] = {bir.x, bir.y, bir.z, bir.w}, bh_r[4] = {bhr.x, bhr.y, bhr.z, bhr.w};
                    float bi_z[4] = {biz.x, biz.y, biz.z, biz.w}, bh_z[4] = {bhz.x, bhz.y, bhz.z, bhz.w};
                    float bi_n[4] = {bin.x, bin.y, bin.z, bin.w}, bh_n[4] = {bhn.x, bhn.y, bhn.z, bhn.w};
                    float dvv[4]  = {dv.x, dv.y, dv.z, dv.w};
#pragma unroll
                    for (int i = 0; i < 4; ++i) {
                        float r  = sigm((gi_r[i] + bi_r[i]) + (gh_r[i] + bh_r[i]));
                        float zt = sigm((gi_z[i] + bi_z[i]) + (gh_z[i] + bh_z[i]));
                        float n  = tanhf((gi_n[i] + bi_n[i]) + r * (gh_n[i] + bh_n[i]));
                        o[i] = (1.f - zt) * n + zt * dvv[i];
                    }
                }
                float4 dn = make_float4(o[0], o[1], o[2], o[3]);
                *(float4 *)(g_det + (size_t)nxt * 65536 + (size_t)b * 1024 + j) = dn;
                *(float4 *)(out_l + (size_t)b * T * OO + (size_t)t * OO + 128 + j) = dn;
            } else if (bx < 128) {
                int jj = bx - 64, ntile = jj >> 3, s = jj & 7;
                gemm_tile<0>(X + (size_t)t * 1024, T * 1024, 1024, nullptr, 0,
                             nullptr, 0, nullptr, nullptr, nullptr, 0,
                             q1l + (size_t)1024 * 1024, nullptr, 1 << 30, 1024,
                             g_Pq1 + (size_t)(16 + s) * 65536, 1024,
                             ntile * 128, s * 128, 8, sA, sB);
            }
            gridbar(slot++);

            // P4: q1 det-part (128 jobs, SK=16, 4 chunks)
            if (bx < 128) {
                int ntile = bx >> 4, s = bx & 15;
                gemm_tile<0>(g_det + (size_t)nxt * 65536, 1024, 1024, nullptr, 0,
                             nullptr, 0, nullptr, nullptr, nullptr, 0,
                             q1l, nullptr, 1 << 30, 1024,
                             g_Pq1 + (size_t)s * 65536, 1024,
                             ntile * 128, s * 64, 4, sA, sB);
            }
            gridbar(slot++);

            // P5: q2, A = elu(reduce Pq1{24} + qb1)  (128 jobs, SK=16, 4 chunks)
            if (bx < 128) {
                int ntile = bx >> 4, s = bx & 15;
                gemm_tile<1>(nullptr, 0, 0, nullptr, 0,
                             g_Pq1, 24, qb1l, nullptr, nullptr, 0,
                             q2l, nullptr, 1 << 30, 1024,
                             g_Pq2 + (size_t)s * 65536, 1024,
                             ntile * 128, s * 64, 4, sA, sB);
            }
            gridbar(slot++);

            // P6: heads [wqm | wqs], A = elu(reduce Pq2{16} + qb2)  (32 jobs, 4 chunks)
            if (bx < 32) {
                int ntile = bx >> 4, s = bx & 15;
                gemm_tile<1>(nullptr, 0, 0, nullptr, 0,
                             g_Pq2, 16, qb2l, nullptr, nullptr, 0,
                             wqml, wqsl, 128, 128,
                             g_Ph + (size_t)s * 64 * 256, 256,
                             ntile * 128, s * 64, 4, sA, sB);
            }
            gridbar(slot++);

            cur = nxt;
        }

        // Final flush: sample(T-1)
        if (bx >= 144) {
            int base = (bx - 144) * 256 + tid;
            write_sample(base, bqml, bqsl, NQ, T, T - 1, out_l);
            write_sample(base + 1024, bqml, bqsl, NQ, T, T - 1, out_l);
        }
        gridbar(slot++);
    }
}

// ---------------- host ----------------
extern "C" void kernel_launch(void* const* d_in, const int* in_sizes, int n_in,
                              void* d_out, int out_size) {
    Args a;
    bool dictOrder = (in_sizes[1] == 64 * 36 * 128);
    if (dictOrder) {
        a.X[0] = (const float *)d_in[0]; a.NQ[0] = (const float *)d_in[2];
        a.X[1] = (const float *)d_in[3]; a.NQ[1] = (const float *)d_in[5];
        a.X[2] = (const float *)d_in[6]; a.NQ[2] = (const float *)d_in[8];
    } else {
        for (int l = 0; l < 3; ++l) {
            a.X[l]  = (const float *)d_in[l];
            a.NQ[l] = (const float *)d_in[6 + l];
        }
    }
    a.w1  = (const float *)d_in[9];
    a.b1  = (const float *)d_in[10];
    a.gwi = (const float *)d_in[11];
    a.gwh = (const float *)d_in[12];
    a.gbi = (const float *)d_in[13];
    a.gbh = (const float *)d_in[14];
    a.q1  = (const float *)d_in[21];
    a.qb1 = (const float *)d_in[22];
    a.q2  = (const float *)d_in[23];
    a.qb2 = (const float *)d_in[24];
    a.wqm = (const float *)d_in[25];
    a.bqm = (const float *)d_in[26];
    a.wqs = (const float *)d_in[27];
    a.bqs = (const float *)d_in[28];
    a.out0 = (float *)d_out;

    cwvae_persist<<<G, 256>>>(a);
    (void)n_in; (void)out_size;
}

// round 16
// speedup vs baseline: 1.2096x; 1.2096x over previous
#include <cuda_runtime.h>
#include <cuda_bf16.h>
#include <math.h>
#include <stdint.h>

#define G    148
#define OO   1152
typedef unsigned long long ull;

// ---------------- scratch ----------------
__device__ float g_Pw1[5 * 64 * 1024];
__device__ float g_Pgh[4 * 64 * 3072];
__device__ float g_Pgi[6 * 64 * 3072];
__device__ float g_Pq1[16 * 64 * 1024];
__device__ float g_Pq2[16 * 64 * 1024];
__device__ float g_Ph [16 * 64 * 256];
__device__ float g_det[2 * 64 * 1024];
__device__ float g_out1[64 * 6 * OO];
__device__ float g_out2[64 * 1 * OO];
__device__ unsigned g_grp[512][8];
__device__ unsigned g_root[512];

// ---------------- helpers ----------------
__device__ __forceinline__ float eluf(float x)  { return x > 0.f ? x : (expf(x) - 1.f); }
__device__ __forceinline__ float sigm(float x)  { return 1.f / (1.f + expf(-x)); }
__device__ __forceinline__ float softp(float x) { return x > 20.f ? x : log1pf(expf(x)); }

__device__ __forceinline__ float4 ldcg4(const float *p) {
    return __ldcg((const float4 *)p);
}

// Two-level replay-safe grid barrier (R9-proven), no trailing acquire fence:
// cross-phase data is read via ldcg4 (L2 is the coherence point).
__device__ __forceinline__ void gridbar(int slot) {
    __syncthreads();
    if (threadIdx.x == 0) {
        __threadfence();
        const int g = blockIdx.x & 7;
        const unsigned gsz = (g < 4) ? 19u : 18u;   // 4*19 + 4*18 = 148
        unsigned old = atomicAdd(&g_grp[slot][g], 1u);
        unsigned r = old / gsz;
        if (old % gsz == gsz - 1u)
            atomicAdd(&g_root[slot], 1u);
        unsigned target = (r + 1u) * 8u;
        volatile unsigned *p = &g_root[slot];
        while (*p < target) { }
    }
    __syncthreads();
}

__device__ __forceinline__ unsigned su32(const void *p) {
    return (unsigned)__cvta_generic_to_shared(p);
}
__device__ __forceinline__ void ldm4(unsigned addr, unsigned *r) {
    asm volatile("ldmatrix.sync.aligned.m8n8.x4.shared.b16 {%0,%1,%2,%3}, [%4];"
                 : "=r"(r[0]), "=r"(r[1]), "=r"(r[2]), "=r"(r[3]) : "r"(addr));
}
__device__ __forceinline__ void ldm4t(unsigned addr, unsigned *r) {
    asm volatile("ldmatrix.sync.aligned.m8n8.x4.trans.shared.b16 {%0,%1,%2,%3}, [%4];"
                 : "=r"(r[0]), "=r"(r[1]), "=r"(r[2]), "=r"(r[3]) : "r"(addr));
}
#define MMA(cp, a, b0, b1)                                                          \
    asm volatile("mma.sync.aligned.m16n8k16.row.col.f32.bf16.bf16.f32 "             \
                 "{%0,%1,%2,%3},{%4,%5,%6,%7},{%8,%9},{%0,%1,%2,%3};"               \
                 : "+f"((cp)[0]), "+f"((cp)[1]), "+f"((cp)[2]), "+f"((cp)[3])       \
                 : "r"((a)[0]), "r"((a)[1]), "r"((a)[2]), "r"((a)[3]),              \
                   "r"(b0), "r"(b1))

__device__ __forceinline__ void split4(float4 v, unsigned *hi, unsigned *lo) {
    __nv_bfloat162 h0 = __floats2bfloat162_rn(v.x, v.y);
    __nv_bfloat162 h1 = __floats2bfloat162_rn(v.z, v.w);
    float rx = v.x - __bfloat162float(h0.x), ry = v.y - __bfloat162float(h0.y);
    float rz = v.z - __bfloat162float(h1.x), rw = v.w - __bfloat162float(h1.y);
    __nv_bfloat162 l0 = __floats2bfloat162_rn(rx, ry);
    __nv_bfloat162 l1 = __floats2bfloat162_rn(rz, rw);
    hi[0] = *reinterpret_cast<unsigned *>(&h0);
    hi[1] = *reinterpret_cast<unsigned *>(&h1);
    lo[0] = *reinterpret_cast<unsigned *>(&l0);
    lo[1] = *reinterpret_cast<unsigned *>(&l1);
}

// ---------------- 64x128 tensor-core GEMM tile (3xBF16, fp32 accuracy) ------
// 4-slot smem buffering, one __syncthreads per chunk PAIR.
#define APITCH 24
#define BPITCH 136
#define ASZ    (64 * APITCH)
#define BSZ    (16 * BPITCH)

template <int RED>
__device__ __forceinline__ void gemm_tile(
    const float *A1, int lda1, int K1, const float *A2, int lda2,
    const float *RP, int RSK, const float *Rbias,
    const float *W1, const float *W2, int wsplit, int ldw,
    float *Pslice, int ldP, int n0, int k0, int nchunks,
    unsigned short *sA, unsigned short *sB)
{
    const int tid  = threadIdx.x;
    const int lane = tid & 31;
    const int w    = tid >> 5;
    const int wm   = w >> 2;
    const int wn   = w & 3;
    const int arow = tid >> 2;
    const int akq  = (tid & 3) * 4;

    float acc[2][4][4];
#pragma unroll
    for (int i = 0; i < 2; ++i)
#pragma unroll
        for (int j = 0; j < 4; ++j)
#pragma unroll
            for (int q = 0; q < 4; ++q) acc[i][j][q] = 0.f;

    auto loadA = [&](int kb) -> float4 {
        int k = kb + akq;
        float4 v = make_float4(0.f, 0.f, 0.f, 0.f);
        if (RED) {
            const float *p = RP + (size_t)arow * 1024 + k;
            for (int s = 0; s < RSK; ++s) {
                float4 t = ldcg4(p + (size_t)s * 64 * 1024);
                v.x += t.x; v.y += t.y; v.z += t.z; v.w += t.w;
            }
            float4 b = *(const float4 *)(Rbias + k);
            v.x = eluf(v.x + b.x); v.y = eluf(v.y + b.y);
            v.z = eluf(v.z + b.z); v.w = eluf(v.w + b.w);
        } else {
            if (k < K1) {
                if (A1) v = ldcg4(A1 + (size_t)arow * lda1 + k);
            } else {
                if (A2) v = ldcg4(A2 + (size_t)arow * lda2 + (k - K1));
            }
        }
        return v;
    };

    float4 wV[2];
    auto loadW = [&](int kb) {
#pragma unroll
        for (int i = 0; i < 2; ++i) {
            int unit = tid + 256 * i;
            int wr = unit >> 5;
            int wc = (unit & 31) * 4;
            int col = n0 + wc;
            const float *wp = (col < wsplit)
                ? (W1 + (size_t)(kb + wr) * ldw + col)
                : (W2 + (size_t)(kb + wr) * ldw + (col - wsplit));
            wV[i] = *(const float4 *)wp;
        }
    };
    auto storeAB = [&](int slot, float4 aV) {
        unsigned hi[2], lo[2];
        split4(aV, hi, lo);
        unsigned short *da = sA + (size_t)slot * 2 * ASZ + arow * APITCH + akq;
        *(uint2 *)da = make_uint2(hi[0], hi[1]);
        *(uint2 *)(da + ASZ) = make_uint2(lo[0], lo[1]);
#pragma unroll
        for (int i = 0; i < 2; ++i) {
            int unit = tid + 256 * i;
            int wr = unit >> 5;
            int wc = (unit & 31) * 4;
            split4(wV[i], hi, lo);
            unsigned short *db = sB + (size_t)slot * 2 * BSZ + wr * BPITCH + wc;
            *(uint2 *)db = make_uint2(hi[0], hi[1]);
            *(uint2 *)(db + BSZ) = make_uint2(lo[0], lo[1]);
        }
    };

    const int gq = lane >> 3, rq = lane & 7;
    const unsigned aLane = ((wm * 32 + (gq & 1) * 8 + rq) * APITCH + (gq >> 1) * 8) * 2;
    const unsigned bLane = (((gq & 1) * 8 + rq) * BPITCH + wn * 32 + (gq >> 1) * 8) * 2;
    const unsigned sAu = su32(sA), sBu = su32(sB);

    auto mma_chunk = [&](int slot) {
        unsigned baseAhi = sAu + slot * (2 * ASZ * 2);
        unsigned baseAlo = baseAhi + ASZ * 2;
        unsigned baseBhi = sBu + slot * (2 * BSZ * 2);
        unsigned baseBlo = baseBhi + BSZ * 2;
        unsigned ah[2][4], al[2][4], bh[8], bl[8];
        ldm4(baseAhi + aLane, ah[0]);
        ldm4(baseAhi + aLane + 16 * APITCH * 2, ah[1]);
        ldm4(baseAlo + aLane, al[0]);
        ldm4(baseAlo + aLane + 16 * APITCH * 2, al[1]);
        ldm4t(baseBhi + bLane, bh);
        ldm4t(baseBhi + bLane + 32, bh + 4);
        ldm4t(baseBlo + bLane, bl);
        ldm4t(baseBlo + bLane + 32, bl + 4);
#pragma unroll
        for (int mt = 0; mt < 2; ++mt) {
#pragma unroll
            for (int nt = 0; nt < 4; ++nt) {
                unsigned b0 = bh[nt * 2], b1 = bh[nt * 2 + 1];
                MMA(acc[mt][nt], ah[mt], b0, b1);
                MMA(acc[mt][nt], ah[mt], bl[nt * 2], bl[nt * 2 + 1]);
                MMA(acc[mt][nt], al[mt], b0, b1);
            }
        }
    };

    // prolog: fill slots 0 and 1
    {
        float4 aV = loadA(k0);
        loadW(k0);
        storeAB(0, aV);
        if (nchunks > 1) {
            aV = loadA(k0 + 16);
            loadW(k0 + 16);
            storeAB(1, aV);
        }
    }
    __syncthreads();

    for (int c = 0; c < nchunks; c += 2) {
        // sub-chunk 0: prefetch c+2, compute c, store c+2
        if (c + 2 < nchunks) {
            float4 aV = loadA(k0 + (c + 2) * 16);
            loadW(k0 + (c + 2) * 16);
            mma_chunk(c & 3);
            storeAB((c + 2) & 3, aV);
        } else {
            mma_chunk(c & 3);
        }
        // sub-chunk 1: prefetch c+3, compute c+1, store c+3
        if (c + 1 < nchunks) {
            if (c + 3 < nchunks) {
                float4 aV = loadA(k0 + (c + 3) * 16);
                loadW(k0 + (c + 3) * 16);
                mma_chunk((c + 1) & 3);
                storeAB((c + 3) & 3, aV);
            } else {
                mma_chunk((c + 1) & 3);
            }
        }
        __syncthreads();
    }

    const int tr = lane >> 2, tc = (lane & 3) * 2;
#pragma unroll
    for (int mt = 0; mt < 2; ++mt) {
#pragma unroll
        for (int nt = 0; nt < 4; ++nt) {
            int row = wm * 32 + mt * 16 + tr;
            int col = n0 + wn * 32 + nt * 8 + tc;
            *(float2 *)&Pslice[(size_t)row * ldP + col] =
                make_float2(acc[mt][nt][0], acc[mt][nt][1]);
            *(float2 *)&Pslice[(size_t)(row + 8) * ldP + col] =
                make_float2(acc[mt][nt][2], acc[mt][nt][3]);
        }
    }
}

// ---------------- kernel ----------------
struct Args {
    const float *X[3], *NQ[3];
    const float *w1, *b1, *gwi, *gwh, *gbi, *gbh;
    const float *q1, *qb1, *q2, *qb2, *wqm, *bqm, *wqs, *bqs;
    float *out0;
};

__global__ __launch_bounds__(256, 1) void cwvae_persist(Args a) {
    __shared__ __align__(16) unsigned short sA[4 * 2 * ASZ];
    __shared__ __align__(16) unsigned short sB[4 * 2 * BSZ];
    const int bx  = blockIdx.x;
    const int tid = threadIdx.x;
    int slot = 0;

    for (int l = 2; l >= 0; --l) {
        const int T   = (l == 0) ? 36 : (l == 1) ? 6 : 1;
        const int Tup = (l == 0) ? 6 : 1;
        const float *X  = a.X[l];
        const float *NQ = a.NQ[l];
        float *out_l = (l == 0) ? a.out0 : (l == 1) ? g_out1 : g_out2;
        const float *out_up = (l == 0) ? g_out1 : (l == 1) ? g_out2 : nullptr;

        const float *w1l  = a.w1  + (size_t)l * 1280 * 1024;
        const float *b1l  = a.b1  + (size_t)l * 1024;
        const float *gwil = a.gwi + (size_t)l * 1024 * 3072;
        const float *gwhl = a.gwh + (size_t)l * 1024 * 3072;
        const float *gbil = a.gbi + (size_t)l * 3072;
        const float *gbhl = a.gbh + (size_t)l * 3072;
        const float *q1l  = a.q1  + (size_t)l * 2048 * 1024;
        const float *qb1l = a.qb1 + (size_t)l * 1024;
        const float *q2l  = a.q2  + (size_t)l * 1024 * 1024;
        const float *qb2l = a.qb2 + (size_t)l * 1024;
        const float *wqml = a.wqm + (size_t)l * 1024 * 128;
        const float *bqml = a.bqm + (size_t)l * 128;
        const float *wqsl = a.wqs + (size_t)l * 1024 * 128;
        const float *bqsl = a.bqs + (size_t)l * 128;

        {   // zero det[0]
            int idx = bx * 256 + tid;
            if (idx < 16384) *(float4 *)&g_det[idx * 4] = make_float4(0.f, 0.f, 0.f, 0.f);
        }
        gridbar(slot++);

        int cur = 0;
        for (int t = 0; t < T; ++t) {
            const int nxt = cur ^ 1;
            const float *samp = (t > 0) ? out_l + (size_t)(t - 1) * OO : nullptr;
            const float *ctx  = out_up ? out_up + (size_t)(t / 6) * OO : nullptr;

            // P1: w1 partials (40 jobs, SK=5, 16 chunks) + gh partials (96 jobs, 16 chunks)
            if (bx < 40) {
                int ntile = bx / 5, s = bx % 5;
                gemm_tile<0>(samp, T * OO, 128, ctx, Tup * OO, nullptr, 0, nullptr,
                             w1l, nullptr, 1 << 30, 1024,
                             g_Pw1 + (size_t)s * 64 * 1024, 1024,
                             ntile * 128, s * 256, 16, sA, sB);
            } else if (bx < 136) {
                int jj = bx - 40, ntile = jj >> 2, s = jj & 3;
                gemm_tile<0>(g_det + (size_t)cur * 65536, 1024, 1024, nullptr, 0,
                             nullptr, 0, nullptr,
                             gwhl, nullptr, 1 << 30, 3072,
                             g_Pgh + (size_t)s * 64 * 3072, 3072,
                             ntile * 128, s * 256, 16, sA, sB);
            }
            gridbar(slot++);

            // P2: gi = elu(reduce Pw1{5} + b1) @ gwi  (144 jobs, SK=6 uneven)
            if (bx < 144) {
                int ntile = bx / 6, s = bx % 6;
                int k0  = (s < 4) ? s * 176 : (704 + (s - 4) * 160);
                int nch = (s < 4) ? 11 : 10;
                gemm_tile<1>(nullptr, 0, 0, nullptr, 0,
                             g_Pw1, 5, b1l,
                             gwil, nullptr, 1 << 30, 3072,
                             g_Pgi + (size_t)s * 64 * 3072, 3072,
                             ntile * 128, k0, nch, sA, sB);
            }
            gridbar(slot++);

            // P3: GRU fuse (Pgi 6 slices, Pgh 4 slices)
            {
                int idx = bx * 256 + tid;
                if (idx < 16384) {
                    int b = idx >> 8;
                    int j = (idx & 255) << 2;
                    float4 gir = make_float4(0,0,0,0), giz = gir, gin = gir;
                    float4 ghr = gir, ghz = gir, ghn = gir;
                    for (int s = 0; s < 6; ++s) {
                        const float *base = g_Pgi + ((size_t)s * 64 + b) * 3072;
                        float4 p;
                        p = ldcg4(base + j);        gir.x+=p.x; gir.y+=p.y; gir.z+=p.z; gir.w+=p.w;
                        p = ldcg4(base + 1024 + j); giz.x+=p.x; giz.y+=p.y; giz.z+=p.z; giz.w+=p.w;
                        p = ldcg4(base + 2048 + j); gin.x+=p.x; gin.y+=p.y; gin.z+=p.z; gin.w+=p.w;
                    }
                    for (int s = 0; s < 4; ++s) {
                        const float *base = g_Pgh + ((size_t)s * 64 + b) * 3072;
                        float4 p;
                        p = ldcg4(base + j);        ghr.x+=p.x; ghr.y+=p.y; ghr.z+=p.z; ghr.w+=p.w;
                        p = ldcg4(base + 1024 + j); ghz.x+=p.x; ghz.y+=p.y; ghz.z+=p.z; ghz.w+=p.w;
                        p = ldcg4(base + 2048 + j); ghn.x+=p.x; ghn.y+=p.y; ghn.z+=p.z; ghn.w+=p.w;
                    }
                    float4 bir = *(const float4 *)(gbil + j),        bhr = *(const float4 *)(gbhl + j);
                    float4 biz = *(const float4 *)(gbil + 1024 + j), bhz = *(const float4 *)(gbhl + 1024 + j);
                    float4 bin = *(const float4 *)(gbil + 2048 + j), bhn = *(const float4 *)(gbhl + 2048 + j);
                    float4 dv  = ldcg4(g_det + (size_t)cur * 65536 + (size_t)b * 1024 + j);
                    float o[4];
                    {
                        float gi_r[4] = {gir.x, gir.y, gir.z, gir.w}, gi_z[4] = {giz.x, giz.y, giz.z, giz.w};
                        float gi_n[4] = {gin.x, gin.y, gin.z, gin.w};
                        float gh_r[4] = {ghr.x, ghr.y, ghr.z, ghr.w}, gh_z[4] = {ghz.x, ghz.y, ghz.z, ghz.w};
                        float gh_n[4] = {ghn.x, ghn.y, ghn.z, ghn.w};
                        float bi_r[4] = {bir.x, bir.y, bir.z, bir.w}, bh_r[4] = {bhr.x, bhr.y, bhr.z, bhr.w};
                        float bi_z[4] = {biz.x, biz.y, biz.z, biz.w}, bh_z[4] = {bhz.x, bhz.y, bhz.z, bhz.w};
                        float bi_n[4] = {bin.x, bin.y, bin.z, bin.w}, bh_n[4] = {bhn.x, bhn.y, bhn.z, bhn.w};
                        float dvv[4]  = {dv.x, dv.y, dv.z, dv.w};
#pragma unroll
                        for (int i = 0; i < 4; ++i) {
                            float r  = sigm((gi_r[i] + bi_r[i]) + (gh_r[i] + bh_r[i]));
                            float zt = sigm((gi_z[i] + bi_z[i]) + (gh_z[i] + bh_z[i]));
                            float n  = tanhf((gi_n[i] + bi_n[i]) + r * (gh_n[i] + bh_n[i]));
                            o[i] = (1.f - zt) * n + zt * dvv[i];
                        }
                    }
                    float4 dn = make_float4(o[0], o[1], o[2], o[3]);
                    *(float4 *)(g_det + (size_t)nxt * 65536 + (size_t)b * 1024 + j) = dn;
                    *(float4 *)(out_l + (size_t)b * T * OO + (size_t)t * OO + 128 + j) = dn;
                }
            }
            gridbar(slot++);

            // P4: q1 partials, A = [det_new | x]  (128 jobs, SK=16, 8 chunks)
            if (bx < 128) {
                int ntile = bx >> 4, s = bx & 15;
                gemm_tile<0>(g_det + (size_t)nxt * 65536, 1024, 1024,
                             X + (size_t)t * 1024, T * 1024,
                             nullptr, 0, nullptr,
                             q1l, nullptr, 1 << 30, 1024,
                             g_Pq1 + (size_t)s * 65536, 1024,
                             ntile * 128, s * 128, 8, sA, sB);
            }
            gridbar(slot++);

            // P5: q2 partials, A = elu(reduce Pq1{16} + qb1)  (128 jobs, SK=16, 4 chunks)
            if (bx < 128) {
                int ntile = bx >> 4, s = bx & 15;
                gemm_tile<1>(nullptr, 0, 0, nullptr, 0,
                             g_Pq1, 16, qb1l,
                             q2l, nullptr, 1 << 30, 1024,
                             g_Pq2 + (size_t)s * 65536, 1024,
                             ntile * 128, s * 64, 4, sA, sB);
            }
            gridbar(slot++);

            // P6: heads [wqm | wqs], A = elu(reduce Pq2{16} + qb2)  (32 jobs, 4 chunks)
            if (bx < 32) {
                int ntile = bx >> 4, s = bx & 15;
                gemm_tile<1>(nullptr, 0, 0, nullptr, 0,
                             g_Pq2, 16, qb2l,
                             wqml, wqsl, 128, 128,
                             g_Ph + (size_t)s * 64 * 256, 256,
                             ntile * 128, s * 64, 4, sA, sB);
            }
            gridbar(slot++);

            // P7: head fin
            {
                int idx = bx * 256 + tid;
                if (idx < 2048) {
                    int b = idx >> 5;
                    int c = (idx & 31) << 2;
                    float4 m = make_float4(0,0,0,0), sp = m;
                    for (int s = 0; s < 16; ++s) {
                        const float *base = g_Ph + ((size_t)s * 64 + b) * 256;
                        float4 p0 = ldcg4(base + c);
                        float4 p1 = ldcg4(base + 128 + c);
                        m.x += p0.x; m.y += p0.y; m.z += p0.z; m.w += p0.w;
                        sp.x += p1.x; sp.y += p1.y; sp.z += p1.z; sp.w += p1.w;
                    }
                    float4 bm = *(const float4 *)(bqml + c);
                    float4 bs = *(const float4 *)(bqsl + c);
                    float4 e  = *(const float4 *)(NQ + (size_t)b * T * 128 + (size_t)t * 128 + c);
                    float4 o;
                    o.x = (m.x + bm.x) + (softp(sp.x + bs.x) + 1e-4f) * e.x;
                    o.y = (m.y + bm.y) + (softp(sp.y + bs.y) + 1e-4f) * e.y;
                    o.z = (m.z + bm.z) + (softp(sp.z + bs.z) + 1e-4f) * e.z;
                    o.w = (m.w + bm.w) + (softp(sp.w + bs.w) + 1e-4f) * e.w;
                    *(float4 *)(out_l + (size_t)b * T * OO + (size_t)t * OO + c) = o;
                }
            }
            gridbar(slot++);

            cur = nxt;
        }
    }
}

// ---------------- host ----------------
extern "C" void kernel_launch(void* const* d_in, const int* in_sizes, int n_in,
                              void* d_out, int out_size) {
    Args a;
    bool dictOrder = (in_sizes[1] == 64 * 36 * 128);
    if (dictOrder) {
        a.X[0] = (const float *)d_in[0]; a.NQ[0] = (const float *)d_in[2];
        a.X[1] = (const float *)d_in[3]; a.NQ[1] = (const float *)d_in[5];
        a.X[2] = (const float *)d_in[6]; a.NQ[2] = (const float *)d_in[8];
    } else {
        for (int l = 0; l < 3; ++l) {
            a.X[l]  = (const float *)d_in[l];
            a.NQ[l] = (const float *)d_in[6 + l];
        }
    }
    a.w1  = (const float *)d_in[9];
    a.b1  = (const float *)d_in[10];
    a.gwi = (const float *)d_in[11];
    a.gwh = (const float *)d_in[12];
    a.gbi = (const float *)d_in[13];
    a.gbh = (const float *)d_in[14];
    a.q1  = (const float *)d_in[21];
    a.qb1 = (const float *)d_in[22];
    a.q2  = (const float *)d_in[23];
    a.qb2 = (const float *)d_in[24];
    a.wqm = (const float *)d_in[25];
    a.bqm = (const float *)d_in[26];
    a.wqs = (const float *)d_in[27];
    a.bqs = (const float *)d_in[28];
    a.out0 = (float *)d_out;

    cwvae_persist<<<G, 256>>>(a);
    (void)n_in; (void)out_size;
}

// round 17
// speedup vs baseline: 1.3087x; 1.0819x over previous
#include <cuda_runtime.h>
#include <cuda_bf16.h>
#include <math.h>
#include <stdint.h>

#define G    148
#define OO   1152
typedef unsigned long long ull;

// ---------------- scratch ----------------
__device__ float g_Pw1[5 * 64 * 1024];
__device__ float g_Pgh[4 * 64 * 3072];
__device__ float g_Pgi[6 * 64 * 3072];
__device__ float g_Pq1[16 * 64 * 1024];
__device__ float g_Pq2[16 * 64 * 1024];
__device__ float g_Ph [16 * 64 * 256];
__device__ float g_det[2 * 64 * 1024];
__device__ float g_out1[64 * 6 * OO];
__device__ float g_out2[64 * 1 * OO];
__device__ unsigned g_grp[512][8];
__device__ unsigned g_root[512];

// ---------------- helpers ----------------
__device__ __forceinline__ float eluf(float x)  { return x > 0.f ? x : (__expf(x) - 1.f); }
__device__ __forceinline__ float sigm(float x)  { return 1.f / (1.f + __expf(-x)); }
__device__ __forceinline__ float softp(float x) { return x > 20.f ? x : log1pf(__expf(x)); }

__device__ __forceinline__ float4 ldcg4(const float *p) {
    return __ldcg((const float4 *)p);
}

// Two-level replay-safe grid barrier (R9-proven), no trailing acquire fence:
// cross-phase data is read via ldcg4 (L2 is the coherence point).
__device__ __forceinline__ void gridbar(int slot) {
    __syncthreads();
    if (threadIdx.x == 0) {
        __threadfence();
        const int g = blockIdx.x & 7;
        const unsigned gsz = (g < 4) ? 19u : 18u;   // 4*19 + 4*18 = 148
        unsigned old = atomicAdd(&g_grp[slot][g], 1u);
        unsigned r = old / gsz;
        if (old % gsz == gsz - 1u)
            atomicAdd(&g_root[slot], 1u);
        unsigned target = (r + 1u) * 8u;
        volatile unsigned *p = &g_root[slot];
        while (*p < target) { }
    }
    __syncthreads();
}

__device__ __forceinline__ unsigned su32(const void *p) {
    return (unsigned)__cvta_generic_to_shared(p);
}
__device__ __forceinline__ void ldm4(unsigned addr, unsigned *r) {
    asm volatile("ldmatrix.sync.aligned.m8n8.x4.shared.b16 {%0,%1,%2,%3}, [%4];"
                 : "=r"(r[0]), "=r"(r[1]), "=r"(r[2]), "=r"(r[3]) : "r"(addr));
}
__device__ __forceinline__ void ldm4t(unsigned addr, unsigned *r) {
    asm volatile("ldmatrix.sync.aligned.m8n8.x4.trans.shared.b16 {%0,%1,%2,%3}, [%4];"
                 : "=r"(r[0]), "=r"(r[1]), "=r"(r[2]), "=r"(r[3]) : "r"(addr));
}
#define MMA(cp, a, b0, b1)                                                          \
    asm volatile("mma.sync.aligned.m16n8k16.row.col.f32.bf16.bf16.f32 "             \
                 "{%0,%1,%2,%3},{%4,%5,%6,%7},{%8,%9},{%0,%1,%2,%3};"               \
                 : "+f"((cp)[0]), "+f"((cp)[1]), "+f"((cp)[2]), "+f"((cp)[3])       \
                 : "r"((a)[0]), "r"((a)[1]), "r"((a)[2]), "r"((a)[3]),              \
                   "r"(b0), "r"(b1))

__device__ __forceinline__ void split4(float4 v, unsigned *hi, unsigned *lo) {
    __nv_bfloat162 h0 = __floats2bfloat162_rn(v.x, v.y);
    __nv_bfloat162 h1 = __floats2bfloat162_rn(v.z, v.w);
    float rx = v.x - __bfloat162float(h0.x), ry = v.y - __bfloat162float(h0.y);
    float rz = v.z - __bfloat162float(h1.x), rw = v.w - __bfloat162float(h1.y);
    __nv_bfloat162 l0 = __floats2bfloat162_rn(rx, ry);
    __nv_bfloat162 l1 = __floats2bfloat162_rn(rz, rw);
    hi[0] = *reinterpret_cast<unsigned *>(&h0);
    hi[1] = *reinterpret_cast<unsigned *>(&h1);
    lo[0] = *reinterpret_cast<unsigned *>(&l0);
    lo[1] = *reinterpret_cast<unsigned *>(&l1);
}

// ---------------- 64x128 tensor-core GEMM tile (3xBF16, fp32 accuracy) ------
// 8-slot smem pipeline, one __syncthreads per 4-chunk group.
#define APITCH 24
#define BPITCH 136
#define ASZ    (64 * APITCH)
#define BSZ    (16 * BPITCH)
#define NSLOT  8
#define SMEM_BYTES ((NSLOT * 2 * ASZ + NSLOT * 2 * BSZ) * 2)

template <int RED>
__device__ __forceinline__ void gemm_tile(
    const float *A1, int lda1, int K1, const float *A2, int lda2,
    const float *RP, int RSK, const float *Rbias,
    const float *W1, const float *W2, int wsplit, int ldw,
    float *Pslice, int ldP, int n0, int k0, int nchunks,
    unsigned short *sA, unsigned short *sB)
{
    const int tid  = threadIdx.x;
    const int lane = tid & 31;
    const int w    = tid >> 5;
    const int wm   = w >> 2;
    const int wn   = w & 3;
    const int arow = tid >> 2;
    const int akq  = (tid & 3) * 4;

    float acc[2][4][4];
#pragma unroll
    for (int i = 0; i < 2; ++i)
#pragma unroll
        for (int j = 0; j < 4; ++j)
#pragma unroll
            for (int q = 0; q < 4; ++q) acc[i][j][q] = 0.f;

    auto loadA = [&](int kb) -> float4 {
        int k = kb + akq;
        float4 v = make_float4(0.f, 0.f, 0.f, 0.f);
        if (RED) {
            const float *p = RP + (size_t)arow * 1024 + k;
            for (int s = 0; s < RSK; ++s) {
                float4 t = ldcg4(p + (size_t)s * 64 * 1024);
                v.x += t.x; v.y += t.y; v.z += t.z; v.w += t.w;
            }
            float4 b = *(const float4 *)(Rbias + k);
            v.x = eluf(v.x + b.x); v.y = eluf(v.y + b.y);
            v.z = eluf(v.z + b.z); v.w = eluf(v.w + b.w);
        } else {
            if (k < K1) {
                if (A1) v = ldcg4(A1 + (size_t)arow * lda1 + k);
            } else {
                if (A2) v = ldcg4(A2 + (size_t)arow * lda2 + (k - K1));
            }
        }
        return v;
    };

    float4 wV[2];
    auto loadW = [&](int kb) {
#pragma unroll
        for (int i = 0; i < 2; ++i) {
            int unit = tid + 256 * i;
            int wr = unit >> 5;
            int wc = (unit & 31) * 4;
            int col = n0 + wc;
            const float *wp = (col < wsplit)
                ? (W1 + (size_t)(kb + wr) * ldw + col)
                : (W2 + (size_t)(kb + wr) * ldw + (col - wsplit));
            wV[i] = *(const float4 *)wp;
        }
    };
    auto storeAB = [&](int slot, float4 aV) {
        unsigned hi[2], lo[2];
        split4(aV, hi, lo);
        unsigned short *da = sA + (size_t)slot * 2 * ASZ + arow * APITCH + akq;
        *(uint2 *)da = make_uint2(hi[0], hi[1]);
        *(uint2 *)(da + ASZ) = make_uint2(lo[0], lo[1]);
#pragma unroll
        for (int i = 0; i < 2; ++i) {
            int unit = tid + 256 * i;
            int wr = unit >> 5;
            int wc = (unit & 31) * 4;
            split4(wV[i], hi, lo);
            unsigned short *db = sB + (size_t)slot * 2 * BSZ + wr * BPITCH + wc;
            *(uint2 *)db = make_uint2(hi[0], hi[1]);
            *(uint2 *)(db + BSZ) = make_uint2(lo[0], lo[1]);
        }
    };

    const int gq = lane >> 3, rq = lane & 7;
    const unsigned aLane = ((wm * 32 + (gq & 1) * 8 + rq) * APITCH + (gq >> 1) * 8) * 2;
    const unsigned bLane = (((gq & 1) * 8 + rq) * BPITCH + wn * 32 + (gq >> 1) * 8) * 2;
    const unsigned sAu = su32(sA), sBu = su32(sB);

    auto mma_chunk = [&](int slot) {
        unsigned baseAhi = sAu + slot * (2 * ASZ * 2);
        unsigned baseAlo = baseAhi + ASZ * 2;
        unsigned baseBhi = sBu + slot * (2 * BSZ * 2);
        unsigned baseBlo = baseBhi + BSZ * 2;
        unsigned ah[2][4], al[2][4], bh[8], bl[8];
        ldm4(baseAhi + aLane, ah[0]);
        ldm4(baseAhi + aLane + 16 * APITCH * 2, ah[1]);
        ldm4(baseAlo + aLane, al[0]);
        ldm4(baseAlo + aLane + 16 * APITCH * 2, al[1]);
        ldm4t(baseBhi + bLane, bh);
        ldm4t(baseBhi + bLane + 32, bh + 4);
        ldm4t(baseBlo + bLane, bl);
        ldm4t(baseBlo + bLane + 32, bl + 4);
#pragma unroll
        for (int mt = 0; mt < 2; ++mt) {
#pragma unroll
            for (int nt = 0; nt < 4; ++nt) {
                unsigned b0 = bh[nt * 2], b1 = bh[nt * 2 + 1];
                MMA(acc[mt][nt], ah[mt], b0, b1);
                MMA(acc[mt][nt], ah[mt], bl[nt * 2], bl[nt * 2 + 1]);
                MMA(acc[mt][nt], al[mt], b0, b1);
            }
        }
    };

    // prolog: fill slots 0..3
#pragma unroll
    for (int i = 0; i < 4; ++i) {
        if (i < nchunks) {
            float4 aV = loadA(k0 + i * 16);
            loadW(k0 + i * 16);
            storeAB(i, aV);
        }
    }
    __syncthreads();

    for (int c = 0; c < nchunks; c += 4) {
#pragma unroll
        for (int i = 0; i < 4; ++i) {
            int cc = c + i;
            if (cc < nchunks) {
                int pf = cc + 4;
                if (pf < nchunks) {
                    float4 aV = loadA(k0 + pf * 16);
                    loadW(k0 + pf * 16);
                    mma_chunk(cc & (NSLOT - 1));
                    storeAB(pf & (NSLOT - 1), aV);
                } else {
                    mma_chunk(cc & (NSLOT - 1));
                }
            }
        }
        __syncthreads();
    }

    const int tr = lane >> 2, tc = (lane & 3) * 2;
#pragma unroll
    for (int mt = 0; mt < 2; ++mt) {
#pragma unroll
        for (int nt = 0; nt < 4; ++nt) {
            int row = wm * 32 + mt * 16 + tr;
            int col = n0 + wn * 32 + nt * 8 + tc;
            *(float2 *)&Pslice[(size_t)row * ldP + col] =
                make_float2(acc[mt][nt][0], acc[mt][nt][1]);
            *(float2 *)&Pslice[(size_t)(row + 8) * ldP + col] =
                make_float2(acc[mt][nt][2], acc[mt][nt][3]);
        }
    }
}

// ---------------- kernel ----------------
struct Args {
    const float *X[3], *NQ[3];
    const float *w1, *b1, *gwi, *gwh, *gbi, *gbh;
    const float *q1, *qb1, *q2, *qb2, *wqm, *bqm, *wqs, *bqs;
    float *out0;
};

__global__ __launch_bounds__(256, 1) void cwvae_persist(Args a) {
    extern __shared__ __align__(16) unsigned short smem_dyn[];
    unsigned short *sA = smem_dyn;
    unsigned short *sB = smem_dyn + NSLOT * 2 * ASZ;
    const int bx  = blockIdx.x;
    const int tid = threadIdx.x;
    int slot = 0;

    for (int l = 2; l >= 0; --l) {
        const int T   = (l == 0) ? 36 : (l == 1) ? 6 : 1;
        const int Tup = (l == 0) ? 6 : 1;
        const float *X  = a.X[l];
        const float *NQ = a.NQ[l];
        float *out_l = (l == 0) ? a.out0 : (l == 1) ? g_out1 : g_out2;
        const float *out_up = (l == 0) ? g_out1 : (l == 1) ? g_out2 : nullptr;

        const float *w1l  = a.w1  + (size_t)l * 1280 * 1024;
        const float *b1l  = a.b1  + (size_t)l * 1024;
        const float *gwil = a.gwi + (size_t)l * 1024 * 3072;
        const float *gwhl = a.gwh + (size_t)l * 1024 * 3072;
        const float *gbil = a.gbi + (size_t)l * 3072;
        const float *gbhl = a.gbh + (size_t)l * 3072;
        const float *q1l  = a.q1  + (size_t)l * 2048 * 1024;
        const float *qb1l = a.qb1 + (size_t)l * 1024;
        const float *q2l  = a.q2  + (size_t)l * 1024 * 1024;
        const float *qb2l = a.qb2 + (size_t)l * 1024;
        const float *wqml = a.wqm + (size_t)l * 1024 * 128;
        const float *bqml = a.bqm + (size_t)l * 128;
        const float *wqsl = a.wqs + (size_t)l * 1024 * 128;
        const float *bqsl = a.bqs + (size_t)l * 128;

        {   // zero det[0]
            int idx = bx * 256 + tid;
            if (idx < 16384) *(float4 *)&g_det[idx * 4] = make_float4(0.f, 0.f, 0.f, 0.f);
        }
        gridbar(slot++);

        int cur = 0;
        for (int t = 0; t < T; ++t) {
            const int nxt = cur ^ 1;
            const float *samp = (t > 0) ? out_l + (size_t)(t - 1) * OO : nullptr;
            const float *ctx  = out_up ? out_up + (size_t)(t / 6) * OO : nullptr;

            // P1: w1 partials (40 jobs, SK=5, 16 chunks) + gh partials (96 jobs, 16 chunks)
            if (bx < 40) {
                int ntile = bx / 5, s = bx % 5;
                gemm_tile<0>(samp, T * OO, 128, ctx, Tup * OO, nullptr, 0, nullptr,
                             w1l, nullptr, 1 << 30, 1024,
                             g_Pw1 + (size_t)s * 64 * 1024, 1024,
                             ntile * 128, s * 256, 16, sA, sB);
            } else if (bx < 136) {
                int jj = bx - 40, ntile = jj >> 2, s = jj & 3;
                gemm_tile<0>(g_det + (size_t)cur * 65536, 1024, 1024, nullptr, 0,
                             nullptr, 0, nullptr,
                             gwhl, nullptr, 1 << 30, 3072,
                             g_Pgh + (size_t)s * 64 * 3072, 3072,
                             ntile * 128, s * 256, 16, sA, sB);
            }
            gridbar(slot++);

            // P2: gi = elu(reduce Pw1{5} + b1) @ gwi  (144 jobs, SK=6 uneven)
            if (bx < 144) {
                int ntile = bx / 6, s = bx % 6;
                int k0  = (s < 4) ? s * 176 : (704 + (s - 4) * 160);
                int nch = (s < 4) ? 11 : 10;
                gemm_tile<1>(nullptr, 0, 0, nullptr, 0,
                             g_Pw1, 5, b1l,
                             gwil, nullptr, 1 << 30, 3072,
                             g_Pgi + (size_t)s * 64 * 3072, 3072,
                             ntile * 128, k0, nch, sA, sB);
            }
            gridbar(slot++);

            // P3: GRU fuse (Pgi 6 slices, Pgh 4 slices)
            {
                int idx = bx * 256 + tid;
                if (idx < 16384) {
                    int b = idx >> 8;
                    int j = (idx & 255) << 2;
                    float4 gir = make_float4(0,0,0,0), giz = gir, gin = gir;
                    float4 ghr = gir, ghz = gir, ghn = gir;
                    for (int s = 0; s < 6; ++s) {
                        const float *base = g_Pgi + ((size_t)s * 64 + b) * 3072;
                        float4 p;
                        p = ldcg4(base + j);        gir.x+=p.x; gir.y+=p.y; gir.z+=p.z; gir.w+=p.w;
                        p = ldcg4(base + 1024 + j); giz.x+=p.x; giz.y+=p.y; giz.z+=p.z; giz.w+=p.w;
                        p = ldcg4(base + 2048 + j); gin.x+=p.x; gin.y+=p.y; gin.z+=p.z; gin.w+=p.w;
                    }
                    for (int s = 0; s < 4; ++s) {
                        const float *base = g_Pgh + ((size_t)s * 64 + b) * 3072;
                        float4 p;
                        p = ldcg4(base + j);        ghr.x+=p.x; ghr.y+=p.y; ghr.z+=p.z; ghr.w+=p.w;
                        p = ldcg4(base + 1024 + j); ghz.x+=p.x; ghz.y+=p.y; ghz.z+=p.z; ghz.w+=p.w;
                        p = ldcg4(base + 2048 + j); ghn.x+=p.x; ghn.y+=p.y; ghn.z+=p.z; ghn.w+=p.w;
                    }
                    float4 bir = *(const float4 *)(gbil + j),        bhr = *(const float4 *)(gbhl + j);
                    float4 biz = *(const float4 *)(gbil + 1024 + j), bhz = *(const float4 *)(gbhl + 1024 + j);
                    float4 bin = *(const float4 *)(gbil + 2048 + j), bhn = *(const float4 *)(gbhl + 2048 + j);
                    float4 dv  = ldcg4(g_det + (size_t)cur * 65536 + (size_t)b * 1024 + j);
                    float o[4];
                    {
                        float gi_r[4] = {gir.x, gir.y, gir.z, gir.w}, gi_z[4] = {giz.x, giz.y, giz.z, giz.w};
                        float gi_n[4] = {gin.x, gin.y, gin.z, gin.w};
                        float gh_r[4] = {ghr.x, ghr.y, ghr.z, ghr.w}, gh_z[4] = {ghz.x, ghz.y, ghz.z, ghz.w};
                        float gh_n[4] = {ghn.x, ghn.y, ghn.z, ghn.w};
                        float bi_r[4] = {bir.x, bir.y, bir.z, bir.w}, bh_r[4] = {bhr.x, bhr.y, bhr.z, bhr.w};
                        float bi_z[4] = {biz.x, biz.y, biz.z, biz.w}, bh_z[4] = {bhz.x, bhz.y, bhz.z, bhz.w};
                        float bi_n[4] = {bin.x, bin.y, bin.z, bin.w}, bh_n[4] = {bhn.x, bhn.y, bhn.z, bhn.w};
                        float dvv[4]  = {dv.x, dv.y, dv.z, dv.w};
#pragma unroll
                        for (int i = 0; i < 4; ++i) {
                            float r  = sigm((gi_r[i] + bi_r[i]) + (gh_r[i] + bh_r[i]));
                            float zt = sigm((gi_z[i] + bi_z[i]) + (gh_z[i] + bh_z[i]));
                            float n  = tanhf((gi_n[i] + bi_n[i]) + r * (gh_n[i] + bh_n[i]));
                            o[i] = (1.f - zt) * n + zt * dvv[i];
                        }
                    }
                    float4 dn = make_float4(o[0], o[1], o[2], o[3]);
                    *(float4 *)(g_det + (size_t)nxt * 65536 + (size_t)b * 1024 + j) = dn;
                    *(float4 *)(out_l + (size_t)b * T * OO + (size_t)t * OO + 128 + j) = dn;
                }
            }
            gridbar(slot++);

            // P4: q1 partials, A = [det_new | x]  (128 jobs, SK=16, 8 chunks)
            if (bx < 128) {
                int ntile = bx >> 4, s = bx & 15;
                gemm_tile<0>(g_det + (size_t)nxt * 65536, 1024, 1024,
                             X + (size_t)t * 1024, T * 1024,
                             nullptr, 0, nullptr,
                             q1l, nullptr, 1 << 30, 1024,
                             g_Pq1 + (size_t)s * 65536, 1024,
                             ntile * 128, s * 128, 8, sA, sB);
            }
            gridbar(slot++);

            // P5: q2 partials, A = elu(reduce Pq1{16} + qb1)  (128 jobs, SK=16, 4 chunks)
            if (bx < 128) {
                int ntile = bx >> 4, s = bx & 15;
                gemm_tile<1>(nullptr, 0, 0, nullptr, 0,
                             g_Pq1, 16, qb1l,
                             q2l, nullptr, 1 << 30, 1024,
                             g_Pq2 + (size_t)s * 65536, 1024,
                             ntile * 128, s * 64, 4, sA, sB);
            }
            gridbar(slot++);

            // P6: heads [wqm | wqs], A = elu(reduce Pq2{16} + qb2)  (32 jobs, 4 chunks)
            if (bx < 32) {
                int ntile = bx >> 4, s = bx & 15;
                gemm_tile<1>(nullptr, 0, 0, nullptr, 0,
                             g_Pq2, 16, qb2l,
                             wqml, wqsl, 128, 128,
                             g_Ph + (size_t)s * 64 * 256, 256,
                             ntile * 128, s * 64, 4, sA, sB);
            }
            gridbar(slot++);

            // P7: head fin
            {
                int idx = bx * 256 + tid;
                if (idx < 2048) {
                    int b = idx >> 5;
                    int c = (idx & 31) << 2;
                    float4 m = make_float4(0,0,0,0), sp = m;
                    for (int s = 0; s < 16; ++s) {
                        const float *base = g_Ph + ((size_t)s * 64 + b) * 256;
                        float4 p0 = ldcg4(base + c);
                        float4 p1 = ldcg4(base + 128 + c);
                        m.x += p0.x; m.y += p0.y; m.z += p0.z; m.w += p0.w;
                        sp.x += p1.x; sp.y += p1.y; sp.z += p1.z; sp.w += p1.w;
                    }
                    float4 bm = *(const float4 *)(bqml + c);
                    float4 bs = *(const float4 *)(bqsl + c);
                    float4 e  = *(const float4 *)(NQ + (size_t)b * T * 128 + (size_t)t * 128 + c);
                    float4 o;
                    o.x = (m.x + bm.x) + (softp(sp.x + bs.x) + 1e-4f) * e.x;
                    o.y = (m.y + bm.y) + (softp(sp.y + bs.y) + 1e-4f) * e.y;
                    o.z = (m.z + bm.z) + (softp(sp.z + bs.z) + 1e-4f) * e.z;
                    o.w = (m.w + bm.w) + (softp(sp.w + bs.w) + 1e-4f) * e.w;
                    *(float4 *)(out_l + (size_t)b * T * OO + (size_t)t * OO + c) = o;
                }
            }
            gridbar(slot++);

            cur = nxt;
        }
    }
}

// ---------------- host ----------------
extern "C" void kernel_launch(void* const* d_in, const int* in_sizes, int n_in,
                              void* d_out, int out_size) {
    Args a;
    bool dictOrder = (in_sizes[1] == 64 * 36 * 128);
    if (dictOrder) {
        a.X[0] = (const float *)d_in[0]; a.NQ[0] = (const float *)d_in[2];
        a.X[1] = (const float *)d_in[3]; a.NQ[1] = (const float *)d_in[5];
        a.X[2] = (const float *)d_in[6]; a.NQ[2] = (const float *)d_in[8];
    } else {
        for (int l = 0; l < 3; ++l) {
            a.X[l]  = (const float *)d_in[l];
            a.NQ[l] = (const float *)d_in[6 + l];
        }
    }
    a.w1  = (const float *)d_in[9];
    a.b1  = (const float *)d_in[10];
    a.gwi = (const float *)d_in[11];
    a.gwh = (const float *)d_in[12];
    a.gbi = (const float *)d_in[13];
    a.gbh = (const float *)d_in[14];
    a.q1  = (const float *)d_in[21];
    a.qb1 = (const float *)d_in[22];
    a.q2  = (const float *)d_in[23];
    a.qb2 = (const float *)d_in[24];
    a.wqm = (const float *)d_in[25];
    a.bqm = (const float *)d_in[26];
    a.wqs = (const float *)d_in[27];
    a.bqs = (const float *)d_in[28];
    a.out0 = (float *)d_out;

    static bool attrSet = false;
    if (!attrSet) {
        cudaFuncSetAttribute(cwvae_persist,
                             cudaFuncAttributeMaxDynamicSharedMemorySize, SMEM_BYTES);
        attrSet = true;
    }
    cwvae_persist<<<G, 256, SMEM_BYTES>>>(a);
    (void)n_in; (void)out_size;
}